// round 2
// baseline (speedup 1.0000x reference)
#include <cuda_runtime.h>

// Problem constants (fixed by the reference)
#define BB 16
#define HH 768
#define WW 768
#define KK 512
#define HWSZ (HH * WW)          // 589824
#define TOTAL (BB * HWSZ)       // 9437184
#define VECS_PER_ROW (WW / 4)   // 192
#define TOTAL_VECS (TOTAL / 4)  // 2359296

#define NBLOCKS 1184            // 148 SMs * 8
#define NTHREADS 256

// Persistent state (zero-initialized at module load; reset by last block each launch)
__device__ double g_acc[2];          // [0]=l1 numerator, [1]=l2 numerator
__device__ unsigned int g_done;

__inline__ __device__ float warp_reduce(float v) {
    #pragma unroll
    for (int o = 16; o > 0; o >>= 1) v += __shfl_down_sync(0xffffffffu, v, o);
    return v;
}

__global__ void __launch_bounds__(NTHREADS) fused_loss_kernel(
    const float* __restrict__ pre, const float* __restrict__ gt,
    const int* __restrict__ cors, float* __restrict__ out)
{
    float s1 = 0.f, s2 = 0.f;

    // ---- Bulk pass: grid-stride over float4 vectors ----
    for (int vec = blockIdx.x * NTHREADS + threadIdx.x;
         vec < TOTAL_VECS;
         vec += gridDim.x * NTHREADS)
    {
        const int row  = vec / VECS_PER_ROW;    // global row in [0, B*H)
        const int y    = row % HH;
        const int x0   = (vec % VECS_PER_ROW) * 4;
        const int base = row * WW + x0;

        const float4 c  = *reinterpret_cast<const float4*>(pre + base);
        const float4 g  = *reinterpret_cast<const float4*>(gt  + base);
        const float4 up = (y > 0)      ? *reinterpret_cast<const float4*>(pre + base - WW)
                                       : make_float4(0.f, 0.f, 0.f, 0.f);
        const float4 dn = (y < HH - 1) ? *reinterpret_cast<const float4*>(pre + base + WW)
                                       : make_float4(0.f, 0.f, 0.f, 0.f);
        const float lft = (x0 > 0)      ? __ldg(pre + base - 1) : 0.f;
        const float rgt = (x0 + 4 < WW) ? __ldg(pre + base + 4) : 0.f;

        const float cv[4] = {c.x, c.y, c.z, c.w};
        const float gv[4] = {g.x, g.y, g.z, g.w};
        const float uv[4] = {up.x, up.y, up.z, up.w};
        const float dv[4] = {dn.x, dn.y, dn.z, dn.w};
        const float lv[4] = {lft, c.x, c.y, c.z};
        const float rv[4] = {c.y, c.z, c.w, rgt};

        #pragma unroll
        for (int i = 0; i < 4; i++) {
            const float d   = cv[i] - gv[i];
            const float err = d * d;
            const bool pm = (cv[i] > lv[i]) && (cv[i] > rv[i]) &&
                            (cv[i] > uv[i]) && (cv[i] > dv[i]);
            s1 += pm ? err : 0.f;
            s2 += err + (gv[i] > 0.f ? 4.f * err : 0.f);
        }
    }

    // ---- gt-point correction: l1 += err*(1 - 2*pre_mask) at UNIQUE gt coords ----
    // Blocks 0..BB-1 each handle one batch (4 KB shared coords, O(K) dedup/pt).
    __shared__ int sx[KK];
    __shared__ int sy[KK];
    if (blockIdx.x < BB) {
        const int b = blockIdx.x;
        for (int p = threadIdx.x; p < KK; p += NTHREADS) {
            sx[p] = cors[(b * KK + p) * 2 + 0];
            sy[p] = cors[(b * KK + p) * 2 + 1];
        }
        __syncthreads();
        for (int p = threadIdx.x; p < KK; p += NTHREADS) {
            const int x = sx[p], y = sy[p];
            bool dup = false;
            for (int j = 0; j < p; j++) {
                if (sx[j] == x && sy[j] == y) { dup = true; break; }
            }
            if (!dup) {
                const int base = b * HWSZ + y * WW + x;
                const float cc = pre[base];
                const float l = (x > 0)      ? pre[base - 1]  : 0.f;
                const float r = (x < WW - 1) ? pre[base + 1]  : 0.f;
                const float u = (y > 0)      ? pre[base - WW] : 0.f;
                const float d = (y < HH - 1) ? pre[base + WW] : 0.f;
                const bool pm = (cc > l) && (cc > r) && (cc > u) && (cc > d);
                const float diff = cc - gt[base];
                s1 += (diff * diff) * (pm ? -1.f : 1.f);
            }
        }
    }

    // ---- Block reduction ----
    __shared__ float sh1[NTHREADS / 32], sh2[NTHREADS / 32];
    const int lane = threadIdx.x & 31;
    const int wid  = threadIdx.x >> 5;
    s1 = warp_reduce(s1);
    s2 = warp_reduce(s2);
    if (lane == 0) { sh1[wid] = s1; sh2[wid] = s2; }
    __syncthreads();

    __shared__ bool is_last;
    if (wid == 0) {
        float v1 = (lane < NTHREADS / 32) ? sh1[lane] : 0.f;
        float v2 = (lane < NTHREADS / 32) ? sh2[lane] : 0.f;
        v1 = warp_reduce(v1);
        v2 = warp_reduce(v2);
        if (lane == 0) {
            atomicAdd(&g_acc[0], (double)v1);
            atomicAdd(&g_acc[1], (double)v2);
            __threadfence();
            const unsigned int done = atomicAdd(&g_done, 1u);
            is_last = (done == gridDim.x - 1);
        }
    }
    __syncthreads();

    // ---- Last block finalizes and resets persistent state ----
    if (is_last && threadIdx.x == 0) {
        __threadfence();
        const double total = g_acc[0] + g_acc[1];
        out[0] = (float)(total / (double)BB);
        g_acc[0] = 0.0;
        g_acc[1] = 0.0;
        g_done = 0u;
    }
}

extern "C" void kernel_launch(void* const* d_in, const int* in_sizes, int n_in,
                              void* d_out, int out_size)
{
    const float* pre  = (const float*)d_in[0];
    const float* gt   = (const float*)d_in[1];
    const int*   cors = (const int*)d_in[2];
    float*       out  = (float*)d_out;

    fused_loss_kernel<<<NBLOCKS, NTHREADS>>>(pre, gt, cors, out);
}

// round 3
// speedup vs baseline: 1.0703x; 1.0703x over previous
#include <cuda_runtime.h>

// Problem constants (fixed by the reference)
#define BB 16
#define HH 768
#define WW 768
#define KK 512
#define HWSZ (HH * WW)            // 589824
#define RSTRIP 8                  // rows per thread strip (768 % 8 == 0)
#define VECS_PER_ROW (WW / 4)     // 192
#define CHUNKS ((BB * HH) / RSTRIP)       // 1536
#define ITEMS (CHUNKS * VECS_PER_ROW)     // 294912

#define NTHREADS 256
#define NBLOCKS (ITEMS / NTHREADS)        // 1152, exactly 1 item per thread

// Persistent state (zero-initialized at module load; reset by last block each launch)
__device__ double g_acc[2];          // [0]=l1 numerator, [1]=l2 numerator
__device__ unsigned int g_done;

__inline__ __device__ float warp_reduce(float v) {
    #pragma unroll
    for (int o = 16; o > 0; o >>= 1) v += __shfl_down_sync(0xffffffffu, v, o);
    return v;
}

__global__ void __launch_bounds__(NTHREADS) fused_loss_kernel(
    const float* __restrict__ pre, const float* __restrict__ gt,
    const int* __restrict__ cors, float* __restrict__ out)
{
    float s1 = 0.f, s2 = 0.f;

    // ---- Bulk pass: one 4-wide x 8-row strip per thread, rows rolled in registers ----
    {
        const int item    = blockIdx.x * NTHREADS + threadIdx.x;   // < ITEMS always
        const int vec_col = item % VECS_PER_ROW;
        const int chunk   = item / VECS_PER_ROW;
        const int grow0   = chunk * RSTRIP;          // global row (b*H + y), image-aligned
        const int y0      = grow0 % HH;              // 0..760, step 8
        const int x0      = vec_col * 4;
        const int base0   = grow0 * WW + x0;

        const float4 zero4 = make_float4(0.f, 0.f, 0.f, 0.f);

        // rows y0-1 (up) and y0 (center)
        float4 pa = (y0 > 0) ? *reinterpret_cast<const float4*>(pre + base0 - WW) : zero4;
        float4 pc = *reinterpret_cast<const float4*>(pre + base0);

        #pragma unroll
        for (int r = 0; r < RSTRIP; r++) {
            const int rowbase = base0 + r * WW;
            const bool has_dn = (y0 + r) < (HH - 1);   // only false for r=7 of last chunk
            const float4 pn = has_dn ? *reinterpret_cast<const float4*>(pre + rowbase + WW)
                                     : zero4;
            const float4 g  = *reinterpret_cast<const float4*>(gt + rowbase);
            const float lft = (x0 > 0)      ? __ldg(pre + rowbase - 1) : 0.f;
            const float rgt = (x0 + 4 < WW) ? __ldg(pre + rowbase + 4) : 0.f;

            const float cv[4] = {pc.x, pc.y, pc.z, pc.w};
            const float gv[4] = {g.x,  g.y,  g.z,  g.w};
            const float uv[4] = {pa.x, pa.y, pa.z, pa.w};
            const float dv[4] = {pn.x, pn.y, pn.z, pn.w};
            const float lv[4] = {lft,  pc.x, pc.y, pc.z};
            const float rv[4] = {pc.y, pc.z, pc.w, rgt};

            #pragma unroll
            for (int i = 0; i < 4; i++) {
                const float d   = cv[i] - gv[i];
                const float err = d * d;
                const bool pm = (cv[i] > lv[i]) && (cv[i] > rv[i]) &&
                                (cv[i] > uv[i]) && (cv[i] > dv[i]);
                s1 += pm ? err : 0.f;
                s2 += err + (gv[i] > 0.f ? 4.f * err : 0.f);
            }

            pa = pc;
            pc = pn;
        }
    }

    // ---- gt-point correction: l1 += err*(1 - 2*pre_mask) at UNIQUE gt coords ----
    __shared__ int sx[KK];
    __shared__ int sy[KK];
    if (blockIdx.x < BB) {
        const int b = blockIdx.x;
        for (int p = threadIdx.x; p < KK; p += NTHREADS) {
            sx[p] = cors[(b * KK + p) * 2 + 0];
            sy[p] = cors[(b * KK + p) * 2 + 1];
        }
        __syncthreads();
        for (int p = threadIdx.x; p < KK; p += NTHREADS) {
            const int x = sx[p], y = sy[p];
            bool dup = false;
            for (int j = 0; j < p; j++) {
                if (sx[j] == x && sy[j] == y) { dup = true; break; }
            }
            if (!dup) {
                const int base = b * HWSZ + y * WW + x;
                const float cc = pre[base];
                const float l = (x > 0)      ? pre[base - 1]  : 0.f;
                const float r = (x < WW - 1) ? pre[base + 1]  : 0.f;
                const float u = (y > 0)      ? pre[base - WW] : 0.f;
                const float d = (y < HH - 1) ? pre[base + WW] : 0.f;
                const bool pm = (cc > l) && (cc > r) && (cc > u) && (cc > d);
                const float diff = cc - gt[base];
                s1 += (diff * diff) * (pm ? -1.f : 1.f);
            }
        }
    }

    // ---- Block reduction + tail ----
    __shared__ float sh1[NTHREADS / 32], sh2[NTHREADS / 32];
    const int lane = threadIdx.x & 31;
    const int wid  = threadIdx.x >> 5;
    s1 = warp_reduce(s1);
    s2 = warp_reduce(s2);
    if (lane == 0) { sh1[wid] = s1; sh2[wid] = s2; }
    __syncthreads();

    __shared__ bool is_last;
    if (wid == 0) {
        float v1 = (lane < NTHREADS / 32) ? sh1[lane] : 0.f;
        float v2 = (lane < NTHREADS / 32) ? sh2[lane] : 0.f;
        v1 = warp_reduce(v1);
        v2 = warp_reduce(v2);
        if (lane == 0) {
            atomicAdd(&g_acc[0], (double)v1);
            atomicAdd(&g_acc[1], (double)v2);
            __threadfence();
            const unsigned int done = atomicAdd(&g_done, 1u);
            is_last = (done == gridDim.x - 1);
        }
    }
    __syncthreads();

    // ---- Last block finalizes and resets persistent state ----
    if (is_last && threadIdx.x == 0) {
        __threadfence();
        const double total = g_acc[0] + g_acc[1];
        out[0] = (float)(total / (double)BB);
        g_acc[0] = 0.0;
        g_acc[1] = 0.0;
        g_done = 0u;
    }
}

extern "C" void kernel_launch(void* const* d_in, const int* in_sizes, int n_in,
                              void* d_out, int out_size)
{
    const float* pre  = (const float*)d_in[0];
    const float* gt   = (const float*)d_in[1];
    const int*   cors = (const int*)d_in[2];
    float*       out  = (float*)d_out;

    fused_loss_kernel<<<NBLOCKS, NTHREADS>>>(pre, gt, cors, out);
}